// round 14
// baseline (speedup 1.0000x reference)
#include <cuda_runtime.h>
#include <cuda_bf16.h>
#include <cstdint>

// ============================================================================
// TTAggregator via mma.sync.m16n8k16 bf16 (base-ISA HMMA; harness ptxas
// targets sm_103, no tcgen05).
//
// Per step d: ris_new[n,c] = sum_{a,b} U_d[a,b,c]*ris[n,a]*h_d[n,b]
//   k = a*16+b (K=256, 16 k-tiles; kt <=> a)
//   A (16x16 per kt, row-major) : A[c][b] = U_d[kt][b][c]      (shared!)
//   B (16x8  per kt, col-major) : B[b][n] = ris[n][kt]*h[n][b] (per-row)
// Split precision: D = Uhi*Zhi + Ulo*Zhi + Uhi*Zlo (lo*lo ~2^-17 dropped).
//
// R14: occupancy push #3 — 32 warps/SM.
//  - TPB=128 (finer allocation granularity), __launch_bounds__(128, 8)
//    -> 64-register budget -> 8 CTAs x 4 warps = 32 warps/SM.
//  - Per-step 64-bit address math hoisted out of the d-loop (persistent
//    per-tile h pointers, +16 floats/step).
// Measured scaling: tensor% ~ linear in warps (38.8/45.6/56.1 @ 8/16/24w);
// tensor work is fixed ~362 us -> at ~72% tensor, ~505 us.
// ============================================================================

static constexpr int NROWS  = 1000000;
static constexpr int DEG    = 10;
static constexpr int TPB    = 128;           // 4 warps
static constexpr int NT     = 2;             // 2 8-row tiles/warp -> 16 rows/warp
static constexpr int ROWS_PER_CTA = 4 * 16;  // 64

static constexpr int RIS_STRIDE = 20;        // floats/row: conflict-free + 16B aligned

// smem (floats): sris 64*20, then U0 256, Uo 256
static constexpr int SM_RIS_F = 0;
static constexpr int SM_U0_F  = ROWS_PER_CTA * RIS_STRIDE;       // 1280
static constexpr int SM_UO_F  = SM_U0_F + 256;
static constexpr int SMEM_BYTES = (SM_UO_F + 256) * 4;           // 7168

// U fragment table: [d(9)][pass(2)][kt(16)][lane(32)] uint4
__device__ uint4 g_ufrag[9 * 2 * 16 * 32];

// ---- packing helpers ----
__device__ __forceinline__ uint32_t pack_hi(float x, float y) {
    uint32_t r;
    asm("prmt.b32 %0, %1, %2, 0x7632;"
        : "=r"(r) : "r"(__float_as_uint(x)), "r"(__float_as_uint(y)));
    return r;
}
__device__ __forceinline__ uint32_t pack_lo_direct(float x, float y) {
    float hx = __uint_as_float(__float_as_uint(x) & 0xffff0000u);
    float hy = __uint_as_float(__float_as_uint(y) & 0xffff0000u);
    float lx = x - hx, ly = y - hy;
    uint32_t r;
    asm("cvt.rn.bf16x2.f32 %0, %1, %2;" : "=r"(r) : "f"(ly), "f"(lx));
    return r;
}

// ---- packed f32x2 ----
__device__ __forceinline__ unsigned long long f2_pack(float x, float y) {
    unsigned long long r;
    asm("mov.b64 %0, {%1, %2};" : "=l"(r) : "f"(x), "f"(y));
    return r;
}
__device__ __forceinline__ unsigned long long f2_mul(unsigned long long a, unsigned long long b) {
    unsigned long long d;
    asm("mul.rn.f32x2 %0, %1, %2;" : "=l"(d) : "l"(a), "l"(b));
    return d;
}
__device__ __forceinline__ unsigned long long f2_fma(unsigned long long a, unsigned long long b,
                                                     unsigned long long c) {
    unsigned long long d;
    asm("fma.rn.f32x2 %0, %1, %2, %3;" : "=l"(d) : "l"(a), "l"(b), "l"(c));
    return d;
}
__device__ __forceinline__ void f2_unpack(unsigned long long v, float& x, float& y) {
    asm("mov.b64 {%0, %1}, %2;" : "=f"(x), "=f"(y) : "l"(v));
}

struct F4 { float x, y, z, w; };

__device__ __forceinline__ void mma16816(F4& d, const uint4& a, uint32_t b0, uint32_t b1) {
    asm volatile(
        "mma.sync.aligned.m16n8k16.row.col.f32.bf16.bf16.f32 "
        "{%0,%1,%2,%3}, {%4,%5,%6,%7}, {%8,%9}, {%0,%1,%2,%3};"
        : "+f"(d.x), "+f"(d.y), "+f"(d.z), "+f"(d.w)
        : "r"(a.x), "r"(a.y), "r"(a.z), "r"(a.w), "r"(b0), "r"(b1));
}

// ---- pre-kernel: build U hi/lo A-fragments in mma fragment order ----
__global__ void build_ufrag_kernel(const float* __restrict__ Ur)
{
    int i = blockIdx.x * blockDim.x + threadIdx.x;   // 0 .. 9*16*32-1
    if (i >= 9 * 16 * 32) return;
    int d  = i >> 9;
    int kt = (i >> 5) & 15;
    int ln = i & 31;
    int lm = ln & 3, lg = ln >> 2;
    const float* Ua = Ur + d * 4096 + kt * 256;      // [b][c]
    float u00 = Ua[(2*lm    )*16 + lg    ], u01 = Ua[(2*lm + 1)*16 + lg    ];
    float u10 = Ua[(2*lm    )*16 + lg + 8], u11 = Ua[(2*lm + 1)*16 + lg + 8];
    float u20 = Ua[(2*lm + 8)*16 + lg    ], u21 = Ua[(2*lm + 9)*16 + lg    ];
    float u30 = Ua[(2*lm + 8)*16 + lg + 8], u31 = Ua[(2*lm + 9)*16 + lg + 8];
    uint4 hi = make_uint4(pack_hi(u00,u01), pack_hi(u10,u11),
                          pack_hi(u20,u21), pack_hi(u30,u31));
    uint4 lo = make_uint4(pack_lo_direct(u00,u01), pack_lo_direct(u10,u11),
                          pack_lo_direct(u20,u21), pack_lo_direct(u30,u31));
    g_ufrag[((d*2 + 0)*16 + kt)*32 + ln] = hi;
    g_ufrag[((d*2 + 1)*16 + kt)*32 + ln] = lo;
}

__global__ __launch_bounds__(TPB, 8)
void tt_mma_kernel(const float* __restrict__ ns,
                   const float* __restrict__ U0,
                   const float* __restrict__ Uo,
                   float* __restrict__ out)
{
    extern __shared__ float smf[];
    float* sris = smf + SM_RIS_F;
    float* sU0  = smf + SM_U0_F;
    float* sUo  = smf + SM_UO_F;

    const int tid  = threadIdx.x;
    const int lane = tid & 31;
    const int w    = tid >> 5;
    const int m    = lane & 3;      // threadID_in_group
    const int g    = lane >> 2;     // groupID
    const long long cta_row0 = (long long)blockIdx.x * ROWS_PER_CTA;

    for (int i = tid; i < 256; i += TPB) { sU0[i] = U0[i]; sUo[i] = Uo[i]; }
    __syncthreads();

    // ---- ris0 = U0^T h0, one thread per row (first 64 threads) ----
    if (tid < ROWS_PER_CTA) {
        long long r = cta_row0 + tid; if (r > NROWS - 1) r = NROWS - 1;
        const float* p = ns + (size_t)r * (DEG * 16);
        float h0[16];
        #pragma unroll
        for (int q = 0; q < 4; q++) {
            float4 v = *(const float4*)(p + q * 4);
            h0[4*q] = v.x; h0[4*q+1] = v.y; h0[4*q+2] = v.z; h0[4*q+3] = v.w;
        }
        float acc[16];
        #pragma unroll
        for (int c = 0; c < 16; c++) acc[c] = 0.f;
        #pragma unroll
        for (int b = 0; b < 16; b++) {
            float hb = h0[b];
            #pragma unroll
            for (int c = 0; c < 16; c++) acc[c] = fmaf(sU0[b*16 + c], hb, acc[c]);
        }
        #pragma unroll
        for (int c = 0; c < 16; c++) sris[tid * RIS_STRIDE + c] = acc[c];
    }
    __syncthreads();

    const int rowbase = w * 16;     // warp-exclusive 16 rows in main loop

    // persistent per-tile h pointers (advance by +16 floats per step);
    // hoists all 64-bit row-address math out of the d-loop.
    const float* hp[NT];
    #pragma unroll
    for (int T = 0; T < NT; T++) {
        long long r = cta_row0 + rowbase + T*8 + g; if (r > NROWS - 1) r = NROWS - 1;
        hp[T] = ns + (size_t)r * (DEG * 16) + 2 * m;
    }
    // per-warp ris row bases in smem
    const float* rp0 = &sris[(rowbase + 0*8 + g) * RIS_STRIDE];
    const float* rp1 = &sris[(rowbase + 1*8 + g) * RIS_STRIDE];

    const unsigned long long NEG1   = f2_pack(-1.0f, -1.0f);
    const unsigned long long MASK64 = 0xffff0000ffff0000ull;

    // ================= main loop: 9 TT steps, warps independent =============
    #pragma unroll 1
    for (int d = 1; d < DEG; d++) {
        const uint4* fh = g_ufrag + ((d-1)*2 + 0) * 512;
        const uint4* fl = g_ufrag + ((d-1)*2 + 1) * 512;

        // h values for both tiles: {h[2m],h[2m+1]}, {h[2m+8],h[2m+9]}
        unsigned long long hha[NT], hhb[NT];
        #pragma unroll
        for (int T = 0; T < NT; T++) {
            const float* p = hp[T] + d * 16;
            float2 va = *(const float2*)p;
            float2 vb = *(const float2*)(p + 8);
            hha[T] = f2_pack(va.x, va.y);
            hhb[T] = f2_pack(vb.x, vb.y);
        }

        // 3 chains per tile (UhiZhi, UloZhi, UhiZlo)
        F4 acc[NT][3];
        #pragma unroll
        for (int T = 0; T < NT; T++)
            #pragma unroll
            for (int p = 0; p < 3; p++) acc[T][p] = F4{0,0,0,0};

        #pragma unroll
        for (int kt = 0; kt < 16; kt++) {
            // stream this kt's U fragments (coalesced 512B LDG.128, L1-hot)
            uint4 uh = __ldg(&fh[kt*32 + lane]);
            uint4 ul = __ldg(&fl[kt*32 + lane]);
            float ra[NT] = { rp0[kt], rp1[kt] };   // broadcast LDS.32
            #pragma unroll
            for (int T = 0; T < NT; T++) {
                unsigned long long rr = f2_pack(ra[T], ra[T]);
                unsigned long long za = f2_mul(rr, hha[T]);
                unsigned long long zb = f2_mul(rr, hhb[T]);
                float z0, z1, z2, z3;
                f2_unpack(za, z0, z1);
                f2_unpack(zb, z2, z3);
                uint32_t zh0 = pack_hi(z0, z1);
                uint32_t zh1 = pack_hi(z2, z3);
                mma16816(acc[T][0], uh, zh0, zh1);
                mma16816(acc[T][1], ul, zh0, zh1);
                // lo residuals: exact z - trunc(z) via masked fma (f32x2)
                unsigned long long la = f2_fma(za & MASK64, NEG1, za);
                unsigned long long lb = f2_fma(zb & MASK64, NEG1, zb);
                float l0, l1, l2, l3;
                f2_unpack(la, l0, l1);
                f2_unpack(lb, l2, l3);
                uint32_t zl0, zl1;
                asm("cvt.rn.bf16x2.f32 %0, %1, %2;" : "=r"(zl0) : "f"(l1), "f"(l0));
                asm("cvt.rn.bf16x2.f32 %0, %1, %2;" : "=r"(zl1) : "f"(l3), "f"(l2));
                mma16816(acc[T][2], uh, zl0, zl1);
            }
        }
        __syncwarp();   // all lanes done reading old ris before overwrite

        // D frag: lane holds channels {g, g+8} of rows {2m, 2m+1} per tile
        #pragma unroll
        for (int T = 0; T < NT; T++) {
            const int r0w = rowbase + T*8 + 2*m, r1w = r0w + 1;
            sris[r0w*RIS_STRIDE + g    ] = (acc[T][0].x + acc[T][1].x) + acc[T][2].x;
            sris[r1w*RIS_STRIDE + g    ] = (acc[T][0].y + acc[T][1].y) + acc[T][2].y;
            sris[r0w*RIS_STRIDE + g + 8] = (acc[T][0].z + acc[T][1].z) + acc[T][2].z;
            sris[r1w*RIS_STRIDE + g + 8] = (acc[T][0].w + acc[T][1].w) + acc[T][2].w;
        }
        __syncwarp();
    }

    // Output reads rows written by other warps -> CTA-wide barrier (R11 lesson).
    __syncthreads();

    // ---- output projection: out[c] = sum_a Uo[a,c] * ris[a] ----
    if (tid < ROWS_PER_CTA) {
        const long long orow = cta_row0 + tid;
        if (orow < NROWS) {
            const float4* rp = (const float4*)&sris[tid * RIS_STRIDE];
            float4 q0 = rp[0], q1 = rp[1], q2 = rp[2], q3 = rp[3];
            float rv[16] = { q0.x,q0.y,q0.z,q0.w, q1.x,q1.y,q1.z,q1.w,
                             q2.x,q2.y,q2.z,q2.w, q3.x,q3.y,q3.z,q3.w };
            float o[16];
            #pragma unroll
            for (int c = 0; c < 16; c++) o[c] = 0.f;
            #pragma unroll
            for (int a = 0; a < 16; a++) {
                float ra = rv[a];
                #pragma unroll
                for (int c = 0; c < 16; c++) o[c] = fmaf(sUo[a*16 + c], ra, o[c]);
            }
            float4* op = (float4*)(out + (size_t)orow * 16);
            #pragma unroll
            for (int q = 0; q < 4; q++)
                op[q] = make_float4(o[4*q], o[4*q+1], o[4*q+2], o[4*q+3]);
        }
    }
}

extern "C" void kernel_launch(void* const* d_in, const int* in_sizes, int n_in,
                              void* d_out, int out_size)
{
    const float* ns = (const float*)d_in[0];
    const float* U0 = (const float*)d_in[1];
    const float* Ur = (const float*)d_in[2];
    const float* Uo = (const float*)d_in[3];
    float* out = (float*)d_out;

    // stage 1: build the U fragment table (9*16*32 = 4608 work items)
    build_ufrag_kernel<<<9, 512>>>(Ur);

    // stage 2: main TT aggregation
    int grid = (NROWS + ROWS_PER_CTA - 1) / ROWS_PER_CTA;
    tt_mma_kernel<<<grid, TPB, SMEM_BYTES>>>(ns, U0, Uo, out);
}

// round 15
// speedup vs baseline: 1.1574x; 1.1574x over previous
#include <cuda_runtime.h>
#include <cuda_bf16.h>
#include <cstdint>

// ============================================================================
// TTAggregator via mma.sync.m16n8k16 bf16 (base-ISA HMMA; harness ptxas
// targets sm_103, no tcgen05).
//
// Per step d: ris_new[n,c] = sum_{a,b} U_d[a,b,c]*ris[n,a]*h_d[n,b]
//   k = a*16+b (K=256, 16 k-tiles; kt <=> a)
//   A (16x16 per kt, row-major) : A[c][b] = U_d[kt][b][c]      (shared!)
//   B (16x8  per kt, col-major) : B[b][n] = ris[n][kt]*h[n][b] (per-row)
// Split precision: D = Uhi*Zhi + Ulo*Zhi + Uhi*Zlo (lo*lo ~2^-17 dropped).
//
// R15: 28 spill-free warps/SM. R14 showed forcing 64 regs spills (L2 30%,
// L1 86%, tensor down). Instead: launch_bounds(128,7) = 73-reg budget and
// trim NATURAL usage under it:
//   - grid is exact (1e6 = 15625*64): all tail clamps and long-long row
//     temps removed.
//   - tile-1 h/ris addressing folded into immediate offsets (+1280 floats
//     gmem, +160 floats smem) instead of second pointers.
// Empirical law: tensor% ~ 2.3%/warp (spill-free); tensor-busy ~364 us.
// ============================================================================

static constexpr int NROWS  = 1000000;
static constexpr int DEG    = 10;
static constexpr int TPB    = 128;           // 4 warps
static constexpr int NT     = 2;             // 2 8-row tiles/warp -> 16 rows/warp
static constexpr int ROWS_PER_CTA = 4 * 16;  // 64; 1e6 % 64 == 0 -> exact grid

static constexpr int RIS_STRIDE = 20;        // floats/row: conflict-free + 16B aligned

// smem (floats): sris 64*20, then U0 256, Uo 256
static constexpr int SM_RIS_F = 0;
static constexpr int SM_U0_F  = ROWS_PER_CTA * RIS_STRIDE;       // 1280
static constexpr int SM_UO_F  = SM_U0_F + 256;
static constexpr int SMEM_BYTES = (SM_UO_F + 256) * 4;           // 7168

// U fragment table: [d(9)][pass(2)][kt(16)][lane(32)] uint4
__device__ uint4 g_ufrag[9 * 2 * 16 * 32];

// ---- packing helpers ----
__device__ __forceinline__ uint32_t pack_hi(float x, float y) {
    uint32_t r;
    asm("prmt.b32 %0, %1, %2, 0x7632;"
        : "=r"(r) : "r"(__float_as_uint(x)), "r"(__float_as_uint(y)));
    return r;
}
__device__ __forceinline__ uint32_t pack_lo_direct(float x, float y) {
    float hx = __uint_as_float(__float_as_uint(x) & 0xffff0000u);
    float hy = __uint_as_float(__float_as_uint(y) & 0xffff0000u);
    float lx = x - hx, ly = y - hy;
    uint32_t r;
    asm("cvt.rn.bf16x2.f32 %0, %1, %2;" : "=r"(r) : "f"(ly), "f"(lx));
    return r;
}

// ---- packed f32x2 ----
__device__ __forceinline__ unsigned long long f2_pack(float x, float y) {
    unsigned long long r;
    asm("mov.b64 %0, {%1, %2};" : "=l"(r) : "f"(x), "f"(y));
    return r;
}
__device__ __forceinline__ unsigned long long f2_mul(unsigned long long a, unsigned long long b) {
    unsigned long long d;
    asm("mul.rn.f32x2 %0, %1, %2;" : "=l"(d) : "l"(a), "l"(b));
    return d;
}
__device__ __forceinline__ unsigned long long f2_fma(unsigned long long a, unsigned long long b,
                                                     unsigned long long c) {
    unsigned long long d;
    asm("fma.rn.f32x2 %0, %1, %2, %3;" : "=l"(d) : "l"(a), "l"(b), "l"(c));
    return d;
}
__device__ __forceinline__ void f2_unpack(unsigned long long v, float& x, float& y) {
    asm("mov.b64 {%0, %1}, %2;" : "=f"(x), "=f"(y) : "l"(v));
}

struct F4 { float x, y, z, w; };

__device__ __forceinline__ void mma16816(F4& d, const uint4& a, uint32_t b0, uint32_t b1) {
    asm volatile(
        "mma.sync.aligned.m16n8k16.row.col.f32.bf16.bf16.f32 "
        "{%0,%1,%2,%3}, {%4,%5,%6,%7}, {%8,%9}, {%0,%1,%2,%3};"
        : "+f"(d.x), "+f"(d.y), "+f"(d.z), "+f"(d.w)
        : "r"(a.x), "r"(a.y), "r"(a.z), "r"(a.w), "r"(b0), "r"(b1));
}

// ---- pre-kernel: build U hi/lo A-fragments in mma fragment order ----
__global__ void build_ufrag_kernel(const float* __restrict__ Ur)
{
    int i = blockIdx.x * blockDim.x + threadIdx.x;   // 0 .. 9*16*32-1
    if (i >= 9 * 16 * 32) return;
    int d  = i >> 9;
    int kt = (i >> 5) & 15;
    int ln = i & 31;
    int lm = ln & 3, lg = ln >> 2;
    const float* Ua = Ur + d * 4096 + kt * 256;      // [b][c]
    float u00 = Ua[(2*lm    )*16 + lg    ], u01 = Ua[(2*lm + 1)*16 + lg    ];
    float u10 = Ua[(2*lm    )*16 + lg + 8], u11 = Ua[(2*lm + 1)*16 + lg + 8];
    float u20 = Ua[(2*lm + 8)*16 + lg    ], u21 = Ua[(2*lm + 9)*16 + lg    ];
    float u30 = Ua[(2*lm + 8)*16 + lg + 8], u31 = Ua[(2*lm + 9)*16 + lg + 8];
    uint4 hi = make_uint4(pack_hi(u00,u01), pack_hi(u10,u11),
                          pack_hi(u20,u21), pack_hi(u30,u31));
    uint4 lo = make_uint4(pack_lo_direct(u00,u01), pack_lo_direct(u10,u11),
                          pack_lo_direct(u20,u21), pack_lo_direct(u30,u31));
    g_ufrag[((d*2 + 0)*16 + kt)*32 + ln] = hi;
    g_ufrag[((d*2 + 1)*16 + kt)*32 + ln] = lo;
}

__global__ __launch_bounds__(TPB, 7)
void tt_mma_kernel(const float* __restrict__ ns,
                   const float* __restrict__ U0,
                   const float* __restrict__ Uo,
                   float* __restrict__ out)
{
    extern __shared__ float smf[];
    float* sris = smf + SM_RIS_F;
    float* sU0  = smf + SM_U0_F;
    float* sUo  = smf + SM_UO_F;

    const int tid  = threadIdx.x;
    const int lane = tid & 31;
    const int w    = tid >> 5;
    const int m    = lane & 3;      // threadID_in_group
    const int g    = lane >> 2;     // groupID

    for (int i = tid; i < 256; i += TPB) { sU0[i] = U0[i]; sUo[i] = Uo[i]; }
    __syncthreads();

    // ---- ris0 = U0^T h0, one thread per row (first 64 threads) ----
    // grid is exact: no row clamping anywhere.
    if (tid < ROWS_PER_CTA) {
        const float* p = ns + ((size_t)blockIdx.x * ROWS_PER_CTA + tid) * (DEG * 16);
        float h0[16];
        #pragma unroll
        for (int q = 0; q < 4; q++) {
            float4 v = *(const float4*)(p + q * 4);
            h0[4*q] = v.x; h0[4*q+1] = v.y; h0[4*q+2] = v.z; h0[4*q+3] = v.w;
        }
        float acc[16];
        #pragma unroll
        for (int c = 0; c < 16; c++) acc[c] = 0.f;
        #pragma unroll
        for (int b = 0; b < 16; b++) {
            float hb = h0[b];
            #pragma unroll
            for (int c = 0; c < 16; c++) acc[c] = fmaf(sU0[b*16 + c], hb, acc[c]);
        }
        #pragma unroll
        for (int c = 0; c < 16; c++) sris[tid * RIS_STRIDE + c] = acc[c];
    }
    __syncthreads();

    const int rowbase = w * 16;     // warp-exclusive 16 rows in main loop

    // single h base pointer (tile 0); tile 1 = +8 rows = +1280 floats (immediate)
    const float* hp = ns +
        ((size_t)blockIdx.x * ROWS_PER_CTA + rowbase + g) * (DEG * 16) + 2 * m;
    // single ris base (tile 0); tile 1 = +8 rows * 20 = +160 floats (immediate)
    const float* rp = &sris[(rowbase + g) * RIS_STRIDE];

    const unsigned long long NEG1   = f2_pack(-1.0f, -1.0f);
    const unsigned long long MASK64 = 0xffff0000ffff0000ull;

    // ================= main loop: 9 TT steps, warps independent =============
    #pragma unroll 1
    for (int d = 1; d < DEG; d++) {
        const uint4* fh = g_ufrag + ((d-1)*2 + 0) * 512;
        const uint4* fl = g_ufrag + ((d-1)*2 + 1) * 512;

        // h values for both tiles: {h[2m],h[2m+1]}, {h[2m+8],h[2m+9]}
        unsigned long long hha[NT], hhb[NT];
        #pragma unroll
        for (int T = 0; T < NT; T++) {
            const float* p = hp + T * (8 * DEG * 16) + d * 16;
            float2 va = *(const float2*)p;
            float2 vb = *(const float2*)(p + 8);
            hha[T] = f2_pack(va.x, va.y);
            hhb[T] = f2_pack(vb.x, vb.y);
        }

        // 3 chains per tile (UhiZhi, UloZhi, UhiZlo)
        F4 acc[NT][3];
        #pragma unroll
        for (int T = 0; T < NT; T++)
            #pragma unroll
            for (int p = 0; p < 3; p++) acc[T][p] = F4{0,0,0,0};

        #pragma unroll
        for (int kt = 0; kt < 16; kt++) {
            // stream this kt's U fragments (coalesced 512B LDG.128, L1-hot)
            uint4 uh = __ldg(&fh[kt*32 + lane]);
            uint4 ul = __ldg(&fl[kt*32 + lane]);
            #pragma unroll
            for (int T = 0; T < NT; T++) {
                float ra = rp[T * (8 * RIS_STRIDE) + kt];   // broadcast LDS.32
                unsigned long long rr = f2_pack(ra, ra);
                unsigned long long za = f2_mul(rr, hha[T]);
                unsigned long long zb = f2_mul(rr, hhb[T]);
                float z0, z1, z2, z3;
                f2_unpack(za, z0, z1);
                f2_unpack(zb, z2, z3);
                uint32_t zh0 = pack_hi(z0, z1);
                uint32_t zh1 = pack_hi(z2, z3);
                mma16816(acc[T][0], uh, zh0, zh1);
                mma16816(acc[T][1], ul, zh0, zh1);
                // lo residuals: exact z - trunc(z) via masked fma (f32x2)
                unsigned long long la = f2_fma(za & MASK64, NEG1, za);
                unsigned long long lb = f2_fma(zb & MASK64, NEG1, zb);
                float l0, l1, l2, l3;
                f2_unpack(la, l0, l1);
                f2_unpack(lb, l2, l3);
                uint32_t zl0, zl1;
                asm("cvt.rn.bf16x2.f32 %0, %1, %2;" : "=r"(zl0) : "f"(l1), "f"(l0));
                asm("cvt.rn.bf16x2.f32 %0, %1, %2;" : "=r"(zl1) : "f"(l3), "f"(l2));
                mma16816(acc[T][2], uh, zl0, zl1);
            }
        }
        __syncwarp();   // all lanes done reading old ris before overwrite

        // D frag: lane holds channels {g, g+8} of rows {2m, 2m+1} per tile
        #pragma unroll
        for (int T = 0; T < NT; T++) {
            const int r0w = rowbase + T*8 + 2*m, r1w = r0w + 1;
            sris[r0w*RIS_STRIDE + g    ] = (acc[T][0].x + acc[T][1].x) + acc[T][2].x;
            sris[r1w*RIS_STRIDE + g    ] = (acc[T][0].y + acc[T][1].y) + acc[T][2].y;
            sris[r0w*RIS_STRIDE + g + 8] = (acc[T][0].z + acc[T][1].z) + acc[T][2].z;
            sris[r1w*RIS_STRIDE + g + 8] = (acc[T][0].w + acc[T][1].w) + acc[T][2].w;
        }
        __syncwarp();
    }

    // Output reads rows written by other warps -> CTA-wide barrier (R11 lesson).
    __syncthreads();

    // ---- output projection: out[c] = sum_a Uo[a,c] * ris[a] ----
    if (tid < ROWS_PER_CTA) {
        const float4* rpo = (const float4*)&sris[tid * RIS_STRIDE];
        float4 q0 = rpo[0], q1 = rpo[1], q2 = rpo[2], q3 = rpo[3];
        float rv[16] = { q0.x,q0.y,q0.z,q0.w, q1.x,q1.y,q1.z,q1.w,
                         q2.x,q2.y,q2.z,q2.w, q3.x,q3.y,q3.z,q3.w };
        float o[16];
        #pragma unroll
        for (int c = 0; c < 16; c++) o[c] = 0.f;
        #pragma unroll
        for (int a = 0; a < 16; a++) {
            float ra = rv[a];
            #pragma unroll
            for (int c = 0; c < 16; c++) o[c] = fmaf(sUo[a*16 + c], ra, o[c]);
        }
        float4* op = (float4*)(out + ((size_t)blockIdx.x * ROWS_PER_CTA + tid) * 16);
        #pragma unroll
        for (int q = 0; q < 4; q++)
            op[q] = make_float4(o[4*q], o[4*q+1], o[4*q+2], o[4*q+3]);
    }
}

extern "C" void kernel_launch(void* const* d_in, const int* in_sizes, int n_in,
                              void* d_out, int out_size)
{
    const float* ns = (const float*)d_in[0];
    const float* U0 = (const float*)d_in[1];
    const float* Ur = (const float*)d_in[2];
    const float* Uo = (const float*)d_in[3];
    float* out = (float*)d_out;

    // stage 1: build the U fragment table (9*16*32 = 4608 work items)
    build_ufrag_kernel<<<9, 512>>>(Ur);

    // stage 2: main TT aggregation (grid exact: 1e6 / 64 = 15625)
    int grid = NROWS / ROWS_PER_CTA;
    tt_mma_kernel<<<grid, TPB, SMEM_BYTES>>>(ns, U0, Uo, out);
}